// round 17
// baseline (speedup 1.0000x reference)
#include <cuda_runtime.h>
#include <cstdint>

#define NQ 8
#define HD 256
#define S_TOT 8192
#define PAST 8191
#define HID 1536
#define INTER 6144
#define QDIM 2048
#define SCALE 0.0625f
#define NCHUNK 256          // 8192 / 32
#define CHUNK 32

// -------- scratch (device globals) --------
__device__ float g_qkv[2560];              // q[0:2048] (pre-scaled), k_new[2048:2304], v_new[2304:2560]
__device__ float g_avpart[NCHUNK * 2048];  // per-chunk partial AV
__device__ float g_stm[NCHUNK * 8];
__device__ float g_stl[NCHUNK * 8];
__device__ float g_attn[QDIM];
__device__ float g_h1[HID];                // preset x+bo by k_comb; k_wo atomics add
__device__ float g_gate[INTER];            // preset bg by k_qkv tail blocks; k_gu atomics add
__device__ float g_up[INTER];              // preset bu by k_qkv tail blocks; k_gu atomics add

static __device__ __forceinline__ float4 f4add(float4 a, float4 b) {
    a.x += b.x; a.y += b.y; a.z += b.z; a.w += b.w; return a;
}
static __device__ __forceinline__ void f4fma(float4& a, float s, float4 w) {
    a.x += s * w.x; a.y += s * w.y; a.z += s * w.z; a.w += s * w.w;
}
static __device__ __forceinline__ float gelu_exact(float v) {
    return 0.5f * v * (1.0f + erff(v * 0.70710678118654752f));
}
template<int PMIN>
static __device__ __forceinline__ float4 wred(float4 v) {
#pragma unroll
    for (int off = 16; off >= PMIN; off >>= 1) {
        v.x += __shfl_xor_sync(0xffffffffu, v.x, off);
        v.y += __shfl_xor_sync(0xffffffffu, v.y, off);
        v.z += __shfl_xor_sync(0xffffffffu, v.z, off);
        v.w += __shfl_xor_sync(0xffffffffu, v.w, off);
    }
    return v;
}
static __device__ __forceinline__ uint32_t smem_u32(const void* p) {
    return (uint32_t)__cvta_generic_to_shared(p);
}
// ---- bulk-DMA (TMA-engine) helpers ----
static __device__ __forceinline__ void mb_init(void* m) {
    asm volatile("mbarrier.init.shared.b64 [%0], 1;" :: "r"(smem_u32(m)));
}
static __device__ __forceinline__ void mb_expect(void* m, int bytes) {
    asm volatile("mbarrier.arrive.expect_tx.shared.b64 _, [%0], %1;"
                 :: "r"(smem_u32(m)), "r"(bytes));
}
static __device__ __forceinline__ void bulk_g2s(void* dst, const void* src, int bytes, void* m) {
    asm volatile("cp.async.bulk.shared::cluster.global.mbarrier::complete_tx::bytes "
                 "[%0], [%1], %2, [%3];"
                 :: "r"(smem_u32(dst)), "l"(src), "r"(bytes), "r"(smem_u32(m)) : "memory");
}
static __device__ __forceinline__ void mb_wait(void* m, int parity) {
    asm volatile("{\n\t.reg .pred P;\nWL_%=:\n\t"
                 "mbarrier.try_wait.parity.shared.b64 P, [%0], %1;\n\t"
                 "@!P bra WL_%=;\n\t}"
                 :: "r"(smem_u32(m)), "r"(parity) : "memory");
}

// ============ K0: L2 prefetch of MLP weights (async engine; exits immediately) ============
// 216 blocks x 128 thr. Block b: matrix = b/72; each thread prefetches one 4KB line-run.
__global__ __launch_bounds__(128) void k_pref(
        const char* __restrict__ Wg, const char* __restrict__ Wu,
        const char* __restrict__ Wd) {
    cudaTriggerProgrammaticLaunchCompletion();
    int b = blockIdx.x, t = threadIdx.x;
    const char* base = (b < 72) ? Wg : (b < 144) ? Wu : Wd;
    size_t off = ((size_t)(b % 72) * 128 + t) * 4096;
    asm volatile("cp.async.bulk.prefetch.L2.global [%0], %1;"
                 :: "l"(base + off), "r"(4096) : "memory");
}

// ============ K1: QKV projection (+bias, q pre-scaled); tail blocks preset g_gate/g_up ====
// 344 blocks x 512 thr. (R16 verbatim)
__global__ __launch_bounds__(512) void k_qkv(
        const float* __restrict__ x,
        const float* __restrict__ Wq, const float* __restrict__ bq,
        const float* __restrict__ Wk, const float* __restrict__ bk,
        const float* __restrict__ Wv, const float* __restrict__ bv,
        const float* __restrict__ bg, const float* __restrict__ bu) {
    __shared__ float4 part[16 * 2];
    int t = threadIdx.x, lane = t & 31, wid = t >> 5;
    if (blockIdx.x >= 320) {
        int b = blockIdx.x - 320;          // 0..23
        if (b < 12) g_gate[b * 512 + t] = bg[b * 512 + t];
        else        g_up[(b - 12) * 512 + t] = bu[(b - 12) * 512 + t];
        return;
    }
    int c4 = t & 1, rg = t >> 1;
    int colBase = blockIdx.x * 8;
    const float* W; const float* bias; int ld, wcol; float sc;
    if (blockIdx.x < 256)      { W = Wq; bias = bq; ld = 2048; wcol = colBase;        sc = SCALE; }
    else if (blockIdx.x < 288) { W = Wk; bias = bk; ld = 256;  wcol = colBase - 2048; sc = 1.0f; }
    else                       { W = Wv; bias = bv; ld = 256;  wcol = colBase - 2304; sc = 1.0f; }
    const float* wp = W + wcol + c4 * 4;
    float4 acc = make_float4(0.f, 0.f, 0.f, 0.f);
    int r0 = rg * 6;
#pragma unroll
    for (int i = 0; i < 6; i++) {
        int r = r0 + i;
        float xv = __ldg(x + r);
        float4 w = *(const float4*)(wp + (size_t)r * ld);
        f4fma(acc, xv, w);
    }
    cudaTriggerProgrammaticLaunchCompletion();
    acc = wred<2>(acc);
    if (lane < 2) part[wid * 2 + lane] = acc;
    __syncthreads();
    if (t < 2) {
        float4 s = part[t];
#pragma unroll
        for (int w = 1; w < 16; w++) s = f4add(s, part[w * 2 + t]);
        int col = wcol + t * 4;
        float4 b = *(const float4*)(bias + col);
        s = f4add(s, b);
        s.x *= sc; s.y *= sc; s.z *= sc; s.w *= sc;
        *(float4*)&g_qkv[colBase + t * 4] = s;
    }
}

// ============ K2: flash-decode partial; K+V PRELOADED before grid sync ============
// 256 blocks x 256 thr. (R16 verbatim)
__global__ __launch_bounds__(256) void k_attn(
        const float* __restrict__ kp, const float* __restrict__ vp) {
    __shared__ float s_sm[8][CHUNK];
    __shared__ float4 red[4 * 8 * 64];
    int t = threadIdx.x, lane = t & 31, wid = t >> 5;
    int c = blockIdx.x;
    int sBase = c * CHUNK;
    int d4 = t & 63, g = t >> 6;
    float4 kA[4], kB[4];
#pragma unroll
    for (int i = 0; i < 4; i++) {
        int r = sBase + wid * 4 + i;
        int rc = (r < PAST) ? r : (PAST - 1);
        const float* kr = kp + (size_t)rc * 256;
        kA[i] = *(const float4*)(kr + lane * 8);
        kB[i] = *(const float4*)(kr + lane * 8 + 4);
    }
    float4 vr[8];
#pragma unroll
    for (int j = 0; j < 8; j++) {
        int s = sBase + g * 8 + j;
        int sc2 = (s < PAST) ? s : (PAST - 1);
        vr[j] = *(const float4*)(vp + (size_t)sc2 * 256 + d4 * 4);
    }
    cudaTriggerProgrammaticLaunchCompletion();
    cudaGridDependencySynchronize();
    if (c == NCHUNK - 1) {
#pragma unroll
        for (int i = 0; i < 4; i++) {
            int r = sBase + wid * 4 + i;
            if (r >= PAST) {
                kA[i] = *(const float4*)(g_qkv + 2048 + lane * 8);
                kB[i] = *(const float4*)(g_qkv + 2048 + lane * 8 + 4);
            }
        }
#pragma unroll
        for (int j = 0; j < 8; j++) {
            int s = sBase + g * 8 + j;
            if (s >= PAST) vr[j] = *(const float4*)(g_qkv + 2304 + d4 * 4);
        }
    }
#pragma unroll
    for (int it = 0; it < 2; it++) {
        float a0[8], a1[8];
#pragma unroll
        for (int h = 0; h < 8; h++) {
            float4 qa = *(const float4*)(g_qkv + h * 256 + lane * 8);
            float4 qb = *(const float4*)(g_qkv + h * 256 + lane * 8 + 4);
            float4 ka0 = kA[it * 2], kb0 = kB[it * 2];
            float4 ka1 = kA[it * 2 + 1], kb1 = kB[it * 2 + 1];
            a0[h] = qa.x * ka0.x + qa.y * ka0.y + qa.z * ka0.z + qa.w * ka0.w
                  + qb.x * kb0.x + qb.y * kb0.y + qb.z * kb0.z + qb.w * kb0.w;
            a1[h] = qa.x * ka1.x + qa.y * ka1.y + qa.z * ka1.z + qa.w * ka1.w
                  + qb.x * kb1.x + qb.y * kb1.y + qb.z * kb1.z + qb.w * kb1.w;
        }
#pragma unroll
        for (int h = 0; h < 8; h++) {
#pragma unroll
            for (int off = 16; off; off >>= 1) {
                a0[h] += __shfl_xor_sync(0xffffffffu, a0[h], off);
                a1[h] += __shfl_xor_sync(0xffffffffu, a1[h], off);
            }
        }
        if (lane < 8) {
            s_sm[lane][wid * 4 + it * 2]     = a0[lane];
            s_sm[lane][wid * 4 + it * 2 + 1] = a1[lane];
        }
    }
    __syncthreads();
    {
        float s = s_sm[wid][lane];
        float m = s;
#pragma unroll
        for (int off = 16; off; off >>= 1) m = fmaxf(m, __shfl_xor_sync(0xffffffffu, m, off));
        float p = __expf(s - m);
        float l = p;
#pragma unroll
        for (int off = 16; off; off >>= 1) l += __shfl_xor_sync(0xffffffffu, l, off);
        s_sm[wid][lane] = p;
        if (lane == 0) { g_stm[c * 8 + wid] = m; g_stl[c * 8 + wid] = l; }
    }
    __syncthreads();
    float4 acc[8];
#pragma unroll
    for (int h = 0; h < 8; h++) acc[h] = make_float4(0.f, 0.f, 0.f, 0.f);
#pragma unroll
    for (int j = 0; j < 8; j++) {
        int pos = g * 8 + j;
#pragma unroll
        for (int h = 0; h < 8; h++) f4fma(acc[h], s_sm[h][pos], vr[j]);
    }
#pragma unroll
    for (int h = 0; h < 8; h++) red[g * 512 + h * 64 + d4] = acc[h];
    __syncthreads();
    float4* outp = (float4*)(g_avpart + (size_t)c * 2048);
#pragma unroll
    for (int k = 0; k < 2; k++) {
        int o = t + k * 256;
        float4 s = f4add(f4add(red[o], red[512 + o]), f4add(red[1024 + o], red[1536 + o]));
        outp[o] = s;
    }
}

// ============ K3: combine -> g_attn; preset g_h1 = x + bo ============ (R16 verbatim)
__global__ __launch_bounds__(256) void k_comb(
        const float* __restrict__ x, const float* __restrict__ bo) {
    __shared__ float w_sm[NCHUNK * 8];
    __shared__ float4 red2[256];
    int t = threadIdx.x, lane = t & 31, wid = t >> 5;
    cudaTriggerProgrammaticLaunchCompletion();
    cudaGridDependencySynchronize();
    float mv[8], lv[8];
#pragma unroll
    for (int i = 0; i < 8; i++) {
        int c = lane * 8 + i;
        mv[i] = g_stm[c * 8 + wid];
        lv[i] = g_stl[c * 8 + wid];
    }
    float M = mv[0];
#pragma unroll
    for (int i = 1; i < 8; i++) M = fmaxf(M, mv[i]);
#pragma unroll
    for (int off = 16; off; off >>= 1) M = fmaxf(M, __shfl_xor_sync(0xffffffffu, M, off));
    float L = 0.f;
#pragma unroll
    for (int i = 0; i < 8; i++) L += __expf(mv[i] - M) * lv[i];
#pragma unroll
    for (int off = 16; off; off >>= 1) L += __shfl_xor_sync(0xffffffffu, L, off);
    float invL = 1.0f / L;
#pragma unroll
    for (int i = 0; i < 8; i++) {
        int c = lane * 8 + i;
        w_sm[c * 8 + wid] = __expf(mv[i] - M) * invL;
    }
    if (blockIdx.x < 6) {
        int idx = blockIdx.x * 256 + t;
        g_h1[idx] = x[idx] + bo[idx];
    }
    __syncthreads();
    int oLoc = t >> 3, sl = t & 7;
    int o = blockIdx.x * 32 + oLoc;
    int h = o >> 6;
    float4 acc = make_float4(0.f, 0.f, 0.f, 0.f);
#pragma unroll
    for (int b = 0; b < 4; b++) {
        float4 vv[8];
#pragma unroll
        for (int i = 0; i < 8; i++) {
            int c = sl * 32 + b * 8 + i;
            vv[i] = *(const float4*)(g_avpart + (size_t)c * 2048 + o * 4);
        }
#pragma unroll
        for (int i = 0; i < 8; i++) {
            int c = sl * 32 + b * 8 + i;
            f4fma(acc, w_sm[c * 8 + h], vv[i]);
        }
    }
    red2[t] = acc;
    __syncthreads();
    if (t < 32) {
        float4 s = red2[t * 8];
#pragma unroll
        for (int i = 1; i < 8; i++) s = f4add(s, red2[t * 8 + i]);
        ((float4*)g_attn)[blockIdx.x * 32 + t] = s;
    }
}

// ============ K4: g_h1 += attn @ Wo  (ALL 4 chunks up-front; dyn smem 48KB) ============
// 256 blocks x 256. (R16 verbatim)
__global__ __launch_bounds__(256) void k_wo(const float* __restrict__ Wo) {
    extern __shared__ __align__(128) float dbuf[];   // 4 * 3072
    __shared__ __align__(8) unsigned long long mbar[4];
    int t = threadIdx.x;
    int r0 = blockIdx.x * 8;
    const char* src = (const char*)(Wo + (size_t)r0 * 1536);
    if (t < 4) mb_init(&mbar[t]);
    __syncthreads();
    if (t == 0) {
#pragma unroll
        for (int b = 0; b < 4; b++) {
            mb_expect(&mbar[b], 12288);
            bulk_g2s(dbuf + b * 3072, src + b * 12288, 12288, &mbar[b]);
        }
    }
    cudaTriggerProgrammaticLaunchCompletion();
    cudaGridDependencySynchronize();
    float acc[6];
#pragma unroll
    for (int j = 0; j < 6; j++) acc[j] = 0.f;
#pragma unroll
    for (int c = 0; c < 4; c++) {
        mb_wait(&mbar[c], 0);
        const float* cb = dbuf + c * 3072;
        float x0 = g_attn[r0 + c * 2], x1 = g_attn[r0 + c * 2 + 1];
#pragma unroll
        for (int j = 0; j < 6; j++)
            acc[j] += x0 * cb[j * 256 + t] + x1 * cb[1536 + j * 256 + t];
    }
#pragma unroll
    for (int j = 0; j < 6; j++) atomicAdd(&g_h1[j * 256 + t], acc[j]);
}

// ============ K5: gate/up accumulation (ring-4, dyn smem 48KB) ============
// 387 blocks x 256. b<192: Wg stripe; b<384: Wu stripe; b>=384: preset out = h1+bd.
__global__ __launch_bounds__(256) void k_gu(
        const float* __restrict__ Wg, const float* __restrict__ Wu,
        const float* __restrict__ bd, float* __restrict__ out) {
    extern __shared__ __align__(128) float dbuf[];   // 4 * 3072
    __shared__ __align__(8) unsigned long long mbar[4];
    int t = threadIdx.x, b = blockIdx.x;
    if (b >= 384) {
        cudaTriggerProgrammaticLaunchCompletion();
        cudaGridDependencySynchronize();
        int i0 = (b - 384) * 512 + t;
        out[i0] = g_h1[i0] + bd[i0];
        out[i0 + 256] = g_h1[i0 + 256] + bd[i0 + 256];
        return;
    }
    int mat = (b >= 192);
    int stripe = mat ? (b - 192) : b;
    int r0 = stripe * 8;
    const char* src = (const char*)((mat ? Wu : Wg) + (size_t)r0 * 6144);
    if (t < 4) mb_init(&mbar[t]);
    __syncthreads();
    if (t == 0) {
#pragma unroll
        for (int bb = 0; bb < 4; bb++) {
            mb_expect(&mbar[bb], 12288);
            bulk_g2s(dbuf + bb * 3072, src + bb * 12288, 12288, &mbar[bb]);
        }
    }
    cudaTriggerProgrammaticLaunchCompletion();
    cudaGridDependencySynchronize();
    float acc[24];
#pragma unroll
    for (int j = 0; j < 24; j++) acc[j] = 0.f;
#pragma unroll
    for (int c = 0; c < 16; c++) {
        mb_wait(&mbar[c & 3], (c >> 2) & 1);
        const float* cb = dbuf + (c & 3) * 3072;
        float xv = g_h1[r0 + (c >> 1)];
        int aBase = (c & 1) * 12;
#pragma unroll
        for (int j = 0; j < 12; j++) acc[aBase + j] += xv * cb[j * 256 + t];
        if (c + 4 < 16) {
            __syncthreads();
            if (t == 0) {
                mb_expect(&mbar[c & 3], 12288);
                bulk_g2s(dbuf + (c & 3) * 3072, src + (size_t)(c + 4) * 12288, 12288, &mbar[c & 3]);
            }
        }
    }
    float* dst = mat ? g_up : g_gate;
#pragma unroll
    for (int j = 0; j < 24; j++) atomicAdd(&dst[j * 256 + t], acc[j]);
}

// ============ K6: out += mid @ Wd  (ring-4, dyn smem 48KB) ============
// 384 blocks x 256.
__global__ __launch_bounds__(256) void k_down(
        const float* __restrict__ Wd, float* __restrict__ out) {
    extern __shared__ __align__(128) float dbuf[];   // 4 * 3072
    __shared__ __align__(8) unsigned long long mbar[4];
    __shared__ float mids[16];
    int t = threadIdx.x;
    int r0 = blockIdx.x * 16;
    const char* src = (const char*)(Wd + (size_t)r0 * 1536);
    if (t < 4) mb_init(&mbar[t]);
    __syncthreads();
    if (t == 0) {
#pragma unroll
        for (int b = 0; b < 4; b++) {
            mb_expect(&mbar[b], 12288);
            bulk_g2s(dbuf + b * 3072, src + b * 12288, 12288, &mbar[b]);
        }
    }
    cudaGridDependencySynchronize();
    if (t < 16) mids[t] = gelu_exact(g_gate[r0 + t]) * g_up[r0 + t];
    __syncthreads();
    float acc[6];
#pragma unroll
    for (int j = 0; j < 6; j++) acc[j] = 0.f;
#pragma unroll
    for (int c = 0; c < 8; c++) {
        mb_wait(&mbar[c & 3], (c >> 2) & 1);
        const float* cb = dbuf + (c & 3) * 3072;
        float x0 = mids[c * 2], x1 = mids[c * 2 + 1];
#pragma unroll
        for (int j = 0; j < 6; j++)
            acc[j] += x0 * cb[j * 256 + t] + x1 * cb[1536 + j * 256 + t];
        if (c + 4 < 8) {
            __syncthreads();
            if (t == 0) {
                mb_expect(&mbar[c & 3], 12288);
                bulk_g2s(dbuf + (c & 3) * 3072, src + (size_t)(c + 4) * 12288, 12288, &mbar[c & 3]);
            }
        }
    }
#pragma unroll
    for (int j = 0; j < 6; j++) atomicAdd(&out[j * 256 + t], acc[j]);
}

// ---- host: PDL launch helper ----
template <typename Fn, typename... Args>
static void launch_pdl(Fn fn, int grid, int block, size_t dynSmem, Args... args) {
    cudaLaunchConfig_t cfg = {};
    cfg.gridDim = dim3(grid, 1, 1);
    cfg.blockDim = dim3(block, 1, 1);
    cfg.dynamicSmemBytes = dynSmem;
    cfg.stream = 0;
    cudaLaunchAttribute at[1];
    at[0].id = cudaLaunchAttributeProgrammaticStreamSerialization;
    at[0].val.programmaticStreamSerializationAllowed = 1;
    cfg.attrs = at;
    cfg.numAttrs = 1;
    cudaLaunchKernelEx(&cfg, fn, args...);
}

extern "C" void kernel_launch(void* const* d_in, const int* in_sizes, int n_in,
                              void* d_out, int out_size) {
    const float* x  = (const float*)d_in[0];
    const float* kp = (const float*)d_in[1];
    const float* vp = (const float*)d_in[2];
    const float* Wq = (const float*)d_in[3];
    const float* bq = (const float*)d_in[4];
    const float* Wk = (const float*)d_in[5];
    const float* bk = (const float*)d_in[6];
    const float* Wv = (const float*)d_in[7];
    const float* bv = (const float*)d_in[8];
    const float* Wo = (const float*)d_in[9];
    const float* bo = (const float*)d_in[10];
    const float* Wg = (const float*)d_in[11];
    const float* bg = (const float*)d_in[12];
    const float* Wu = (const float*)d_in[13];
    const float* bu = (const float*)d_in[14];
    const float* Wd = (const float*)d_in[15];
    const float* bd = (const float*)d_in[16];
    float* out = (float*)d_out;

    cudaFuncSetAttribute(k_wo,   cudaFuncAttributeMaxDynamicSharedMemorySize, 49152);
    cudaFuncSetAttribute(k_gu,   cudaFuncAttributeMaxDynamicSharedMemorySize, 49152);
    cudaFuncSetAttribute(k_down, cudaFuncAttributeMaxDynamicSharedMemorySize, 49152);

    k_pref<<<216, 128>>>((const char*)Wg, (const char*)Wu, (const char*)Wd);
    launch_pdl(k_qkv, 344, 512, 0, x, Wq, bq, Wk, bk, Wv, bv, bg, bu);
    launch_pdl(k_attn, 256, 256, 0, kp, vp);
    launch_pdl(k_comb, 16, 256, 0, x, bo);
    launch_pdl(k_wo, 256, 256, 49152, Wo);
    launch_pdl(k_gu, 387, 256, 49152, Wg, Wu, bd, out);
    launch_pdl(k_down, 384, 256, 49152, Wd, out);
}